// round 3
// baseline (speedup 1.0000x reference)
#include <cuda_runtime.h>
#include <math.h>

#define N_NODES 100000
#define F_IN    20
#define F_MID   16

// ---- scratch (no allocations allowed) ----
// Vector-typed so the 128b/64b loads and red.global.add.v4/v2 are aligned.
__device__ float  g_deg [N_NODES];
__device__ float  g_dinv[N_NODES];
__device__ float4 g_y1  [N_NODES * (F_MID / 4)];   // dinv[c] * (x@W1)[c]
__device__ float4 g_acc1[N_NODES * (F_MID / 4)];   // scatter accumulator layer 1
__device__ float2 g_y2  [N_NODES];                 // dinv[c] * (h@W2)[c]
__device__ float2 g_acc2[N_NODES];                 // scatter accumulator layer 2

// ---------------------------------------------------------------------------
// K0: deg = 1 (self loop)
__global__ void k_init_deg() {
    int n = blockIdx.x * blockDim.x + threadIdx.x;
    if (n < N_NODES) g_deg[n] = 1.0f;
}

// K1: deg[row] += 1 per edge  (edge_index is int32 — JAX x64 is off)
__global__ void k_count_deg(const int* __restrict__ rowp, int E) {
    int e = blockIdx.x * blockDim.x + threadIdx.x;
    if (e >= E) return;
    int r = rowp[e];
    if ((unsigned)r < (unsigned)N_NODES)
        atomicAdd(&g_deg[r], 1.0f);
}

// K2: dinv = rsqrt(deg); y1 = dinv * (x @ W1); acc1 = y1 (self-loop init)
__global__ void k_xw1(const float* __restrict__ x, const float* __restrict__ W1) {
    __shared__ float sW[F_IN * F_MID];
    for (int i = threadIdx.x; i < F_IN * F_MID; i += blockDim.x) sW[i] = W1[i];
    __syncthreads();

    int n = blockIdx.x * blockDim.x + threadIdx.x;
    if (n >= N_NODES) return;

    float xi[F_IN];
#pragma unroll
    for (int k = 0; k < F_IN; k++) xi[k] = x[n * F_IN + k];

    float di = rsqrtf(g_deg[n]);
    g_dinv[n] = di;

    float v[F_MID];
#pragma unroll
    for (int f = 0; f < F_MID; f++) {
        float s = 0.0f;
#pragma unroll
        for (int k = 0; k < F_IN; k++) s = fmaf(xi[k], sW[k * F_MID + f], s);
        v[f] = di * s;
    }
#pragma unroll
    for (int j = 0; j < F_MID / 4; j++) {
        float4 q = make_float4(v[4*j], v[4*j+1], v[4*j+2], v[4*j+3]);
        g_y1  [n * (F_MID/4) + j] = q;
        g_acc1[n * (F_MID/4) + j] = q;
    }
}

// K3: per edge: acc1[row][:] += y1[col][:]   (4x red.global.add.v4.f32)
__global__ void k_scatter1(const int* __restrict__ rowp,
                           const int* __restrict__ colp, int E) {
    int e = blockIdx.x * blockDim.x + threadIdx.x;
    if (e >= E) return;
    int r = rowp[e];
    int c = colp[e];
    if ((unsigned)r >= (unsigned)N_NODES || (unsigned)c >= (unsigned)N_NODES) return;
    const float4* src = &g_y1  [(size_t)c * (F_MID/4)];
    float4*       dst = &g_acc1[(size_t)r * (F_MID/4)];
#pragma unroll
    for (int j = 0; j < F_MID / 4; j++) {
        float4 v = __ldg(&src[j]);
        asm volatile("red.global.add.v4.f32 [%0], {%1, %2, %3, %4};"
                     :: "l"(&dst[j]), "f"(v.x), "f"(v.y), "f"(v.z), "f"(v.w)
                     : "memory");
    }
}

// K4: h = relu(dinv*acc1 + b1); y2 = dinv * (h @ W2); acc2 = y2
__global__ void k_xw2(const float* __restrict__ W2, const float* __restrict__ b1) {
    __shared__ float sW[F_MID * 2];
    __shared__ float sb[F_MID];
    if (threadIdx.x < F_MID * 2) sW[threadIdx.x] = W2[threadIdx.x];
    if (threadIdx.x < F_MID)     sb[threadIdx.x] = b1[threadIdx.x];
    __syncthreads();

    int n = blockIdx.x * blockDim.x + threadIdx.x;
    if (n >= N_NODES) return;

    float di = g_dinv[n];
    float z0 = 0.0f, z1 = 0.0f;
#pragma unroll
    for (int j = 0; j < F_MID / 4; j++) {
        float4 a = g_acc1[n * (F_MID/4) + j];
        float av[4] = {a.x, a.y, a.z, a.w};
#pragma unroll
        for (int t = 0; t < 4; t++) {
            int f = 4*j + t;
            float h = fmaxf(fmaf(di, av[t], sb[f]), 0.0f);
            z0 = fmaf(h, sW[f * 2 + 0], z0);
            z1 = fmaf(h, sW[f * 2 + 1], z1);
        }
    }
    float2 v = make_float2(di * z0, di * z1);
    g_y2[n]   = v;
    g_acc2[n] = v;
}

// K5: per edge: acc2[row] += y2[col]   (red.global.add.v2.f32)
__global__ void k_scatter2(const int* __restrict__ rowp,
                           const int* __restrict__ colp, int E) {
    int e = blockIdx.x * blockDim.x + threadIdx.x;
    if (e >= E) return;
    int r = rowp[e];
    int c = colp[e];
    if ((unsigned)r >= (unsigned)N_NODES || (unsigned)c >= (unsigned)N_NODES) return;
    float2 v = __ldg(&g_y2[c]);
    asm volatile("red.global.add.v2.f32 [%0], {%1, %2};"
                 :: "l"(&g_acc2[r]), "f"(v.x), "f"(v.y)
                 : "memory");
}

// K6: out = log_softmax(dinv*acc2 + b2)
__global__ void k_final(const float* __restrict__ b2, float* __restrict__ out) {
    int n = blockIdx.x * blockDim.x + threadIdx.x;
    if (n >= N_NODES) return;
    float di = g_dinv[n];
    float2 a = g_acc2[n];
    float v0 = fmaf(di, a.x, b2[0]);
    float v1 = fmaf(di, a.y, b2[1]);
    float m  = fmaxf(v0, v1);
    float lse = m + logf(expf(v0 - m) + expf(v1 - m));
    out[n * 2 + 0] = v0 - lse;
    out[n * 2 + 1] = v1 - lse;
}

extern "C" void kernel_launch(void* const* d_in, const int* in_sizes, int n_in,
                              void* d_out, int out_size) {
    const float* x  = (const float*)d_in[0];
    const int*   ei = (const int*)d_in[1];     // int32! (JAX x64 disabled)
    const float* W1 = (const float*)d_in[2];
    const float* b1 = (const float*)d_in[3];
    const float* W2 = (const float*)d_in[4];
    const float* b2 = (const float*)d_in[5];
    float*       out = (float*)d_out;

    const int E = in_sizes[1] / 2;
    const int* rowp = ei;       // edge_index[0] = targets
    const int* colp = ei + E;   // edge_index[1] = sources

    const int TB = 256;
    const int gN = (N_NODES + TB - 1) / TB;
    const int gE = (E + TB - 1) / TB;

    k_init_deg <<<gN, TB>>>();
    k_count_deg<<<gE, TB>>>(rowp, E);
    k_xw1      <<<gN, TB>>>(x, W1);
    k_scatter1 <<<gE, TB>>>(rowp, colp, E);
    k_xw2      <<<gN, TB>>>(W2, b1);
    k_scatter2 <<<gE, TB>>>(rowp, colp, E);
    k_final    <<<gN, TB>>>(b2, out);
}